// round 4
// baseline (speedup 1.0000x reference)
#include <cuda_runtime.h>

#define EMBED      128
#define HID        64
#define MAX_NODES  50000
#define EPS_F      1e-10f

// Scratch: PQ[n][0:64] = node_embed[n] @ W1[0:128], PQ[n][64:128] = node_embed[n] @ W1[128:256]
__device__ float g_PQ[(size_t)MAX_NODES * 128];
// 1 if edge_index buffer is int64 (little-endian), 0 if int32.
__device__ int g_idx_is64;

// ---------------------------------------------------------------------------
// Kernel 0: detect edge_index dtype. If the buffer holds int64 node indices
// (< 2^31, nonnegative), every odd 32-bit word is 0. For int32, odd words are
// random indices in [0, 50000) — 64 consecutive zeros is impossible.
// ---------------------------------------------------------------------------
__global__ void detect_idx_dtype_kernel(const int* __restrict__ eidx32, int num_edges)
{
    int n = num_edges < 64 ? num_edges : 64;
    int all_zero = 1;
    for (int i = 0; i < n; i++)
        if (eidx32[2 * i + 1] != 0) { all_zero = 0; break; }
    g_idx_is64 = all_zero;
}

// ---------------------------------------------------------------------------
// Kernel 1: PQ = node_embed(50000x128) @ W_eff(128x128)
// W_eff[k][j] = W1[k][j] (j<64) else W1[128+k][j-64]
// Block: 256 threads, 32 rows x 128 cols per block, 4 rows per warp.
// ---------------------------------------------------------------------------
__global__ void __launch_bounds__(256) pq_gemm_kernel(
    const float* __restrict__ emb,
    const float* __restrict__ W1,
    int num_nodes)
{
    __shared__ float sW[64][128];   // 32KB
    __shared__ float sE[32][64];    // 8KB

    const int tid  = threadIdx.x;
    const int warp = tid >> 5;
    const int lane = tid & 31;
    const int row_base = blockIdx.x * 32;

    float4 acc[4];
    #pragma unroll
    for (int r = 0; r < 4; r++) acc[r] = make_float4(0.f, 0.f, 0.f, 0.f);

    const float4 zero4 = make_float4(0.f, 0.f, 0.f, 0.f);

    for (int kc = 0; kc < 2; kc++) {
        if (kc) __syncthreads();
        // load W chunk: 64 x 128 elements
        for (int i = tid; i < 64 * 128; i += 256) {
            int k = i >> 7;
            int j = i & 127;
            int gk = kc * 64 + k;
            float v = (j < 64) ? W1[gk * 64 + j] : W1[(128 + gk) * 64 + (j - 64)];
            sW[k][j] = v;
        }
        // load emb tile: 32 rows x 64 cols (as float4)
        for (int i = tid; i < 32 * 16; i += 256) {
            int r  = i >> 4;
            int c4 = i & 15;
            int gr = row_base + r;
            float4 v = zero4;
            if (gr < num_nodes)
                v = *reinterpret_cast<const float4*>(&emb[(size_t)gr * 128 + kc * 64 + c4 * 4]);
            *reinterpret_cast<float4*>(&sE[r][c4 * 4]) = v;
        }
        __syncthreads();

        const int j4 = lane * 4;
        #pragma unroll
        for (int kk = 0; kk < 64; kk += 4) {
            float4 e0 = *reinterpret_cast<const float4*>(&sE[warp * 4 + 0][kk]);
            float4 e1 = *reinterpret_cast<const float4*>(&sE[warp * 4 + 1][kk]);
            float4 e2 = *reinterpret_cast<const float4*>(&sE[warp * 4 + 2][kk]);
            float4 e3 = *reinterpret_cast<const float4*>(&sE[warp * 4 + 3][kk]);
            #define FMA4(A, S, W) \
                (A).x = fmaf((S), (W).x, (A).x); \
                (A).y = fmaf((S), (W).y, (A).y); \
                (A).z = fmaf((S), (W).z, (A).z); \
                (A).w = fmaf((S), (W).w, (A).w);
            {
                float4 w = *reinterpret_cast<const float4*>(&sW[kk + 0][j4]);
                FMA4(acc[0], e0.x, w); FMA4(acc[1], e1.x, w);
                FMA4(acc[2], e2.x, w); FMA4(acc[3], e3.x, w);
            }
            {
                float4 w = *reinterpret_cast<const float4*>(&sW[kk + 1][j4]);
                FMA4(acc[0], e0.y, w); FMA4(acc[1], e1.y, w);
                FMA4(acc[2], e2.y, w); FMA4(acc[3], e3.y, w);
            }
            {
                float4 w = *reinterpret_cast<const float4*>(&sW[kk + 2][j4]);
                FMA4(acc[0], e0.z, w); FMA4(acc[1], e1.z, w);
                FMA4(acc[2], e2.z, w); FMA4(acc[3], e3.z, w);
            }
            {
                float4 w = *reinterpret_cast<const float4*>(&sW[kk + 3][j4]);
                FMA4(acc[0], e0.w, w); FMA4(acc[1], e1.w, w);
                FMA4(acc[2], e2.w, w); FMA4(acc[3], e3.w, w);
            }
            #undef FMA4
        }
    }

    #pragma unroll
    for (int r = 0; r < 4; r++) {
        int gr = row_base + warp * 4 + r;
        if (gr < num_nodes)
            *reinterpret_cast<float4*>(&g_PQ[(size_t)gr * 128 + lane * 4]) = acc[r];
    }
}

// ---------------------------------------------------------------------------
// Kernel 2: per-edge MLP tail + gumbel-sigmoid
// 16 threads per edge; each thread owns 4 hidden units (float4).
// ---------------------------------------------------------------------------
__global__ void __launch_bounds__(256) edge_kernel(
    const void* __restrict__ eidx_raw,    // [2, E] int32 or int64 (see g_idx_is64)
    const float* __restrict__ u1,
    const float* __restrict__ u2,
    const float* __restrict__ b1,
    const float* __restrict__ W2,
    const float* __restrict__ b2,
    float* __restrict__ out,
    int num_edges)
{
    const int tid = threadIdx.x;
    const int g   = tid >> 4;    // group within block (0..15)
    const int gl  = tid & 15;    // lane within group
    const long long e_raw = (long long)blockIdx.x * 16 + g;
    // Clamp instead of early-return so shuffle groups stay fully active.
    const bool valid = (e_raw < num_edges);
    const long long e = valid ? e_raw : (long long)(num_edges - 1);

    int row, col;
    if (g_idx_is64) {
        const long long* eidx = (const long long*)eidx_raw;
        row = (int)eidx[e];
        col = (int)eidx[(long long)num_edges + e];
    } else {
        const int* eidx = (const int*)eidx_raw;
        row = eidx[e];
        col = eidx[(long long)num_edges + e];
    }
    const int j0 = gl * 4;

    float4 p  = *reinterpret_cast<const float4*>(&g_PQ[(size_t)row * 128 + j0]);
    float4 q  = *reinterpret_cast<const float4*>(&g_PQ[(size_t)col * 128 + 64 + j0]);
    float4 bb = *reinterpret_cast<const float4*>(&b1[j0]);
    float4 w  = *reinterpret_cast<const float4*>(&W2[j0]);

    float h0 = fmaxf(p.x + q.x + bb.x, 0.f);
    float h1 = fmaxf(p.y + q.y + bb.y, 0.f);
    float h2 = fmaxf(p.z + q.z + bb.z, 0.f);
    float h3 = fmaxf(p.w + q.w + bb.w, 0.f);

    float partial = fmaf(h0, w.x, fmaf(h1, w.y, fmaf(h2, w.z, h3 * w.w)));
    #pragma unroll
    for (int o = 8; o >= 1; o >>= 1)
        partial += __shfl_xor_sync(0xffffffffu, partial, o);

    if (gl == 0 && valid) {
        float logit = partial + b2[0];
        // Accurate log/exp: -log(-log(u)) is ill-conditioned near u->1.
        float v1 = fminf(fmaxf(u1[e], EPS_F), 1.0f - EPS_F);
        float v2 = fminf(fmaxf(u2[e], EPS_F), 1.0f - EPS_F);
        float g1 = -logf(-logf(v1));
        float g2 = -logf(-logf(v2));
        float x  = logit + g1 - g2;
        out[e] = 1.0f / (1.0f + expf(-x));
    }
}

// ---------------------------------------------------------------------------
// Inputs (metadata order): node_embed, edge_index, u1, u2, W1, b1, W2, b2
// Output: float32 [num_edges]
// ---------------------------------------------------------------------------
extern "C" void kernel_launch(void* const* d_in, const int* in_sizes, int n_in,
                              void* d_out, int out_size)
{
    const float* node_embed = (const float*)d_in[0];
    const void*  edge_index = d_in[1];
    const float* u1         = (const float*)d_in[2];
    const float* u2         = (const float*)d_in[3];
    const float* W1         = (const float*)d_in[4];
    const float* b1         = (const float*)d_in[5];
    const float* W2         = (const float*)d_in[6];
    const float* b2         = (const float*)d_in[7];
    float*       out        = (float*)d_out;

    const int num_nodes = in_sizes[0] / EMBED;
    const int num_edges = in_sizes[2];

    detect_idx_dtype_kernel<<<1, 1>>>((const int*)edge_index, num_edges);

    int gemm_blocks = (num_nodes + 31) / 32;
    pq_gemm_kernel<<<gemm_blocks, 256>>>(node_embed, W1, num_nodes);

    int edge_blocks = (num_edges + 15) / 16;
    edge_kernel<<<edge_blocks, 256>>>(edge_index, u1, u2, b1, W2, b2, out, num_edges);
}